// round 7
// baseline (speedup 1.0000x reference)
#include <cuda_runtime.h>
#include <cuda_bf16.h>
#include <cstdint>

// Problem constants
#define B_   4
#define S_   2048
#define D_   1024
#define H_   16
#define DK_  64
#define M_   (B_ * S_)   // 8192

// ---------------------------------------------------------------------------
// Scratch (device globals — no allocations allowed)
// ---------------------------------------------------------------------------
__device__ __nv_bfloat16 g_Xqhi[(size_t)M_ * D_];  // input splits; Xq reused for O
__device__ __nv_bfloat16 g_Xqlo[(size_t)M_ * D_];
__device__ __nv_bfloat16 g_Xkhi[(size_t)M_ * D_];
__device__ __nv_bfloat16 g_Xklo[(size_t)M_ * D_];
__device__ __nv_bfloat16 g_Xvhi[(size_t)M_ * D_];
__device__ __nv_bfloat16 g_Xvlo[(size_t)M_ * D_];
__device__ __nv_bfloat16 g_WQhi[(size_t)D_ * D_];  // transposed weights [N,K]
__device__ __nv_bfloat16 g_WQlo[(size_t)D_ * D_];
__device__ __nv_bfloat16 g_WKhi[(size_t)D_ * D_];
__device__ __nv_bfloat16 g_WKlo[(size_t)D_ * D_];
__device__ __nv_bfloat16 g_WVhi[(size_t)D_ * D_];
__device__ __nv_bfloat16 g_WVlo[(size_t)D_ * D_];
__device__ __nv_bfloat16 g_WOhi[(size_t)D_ * D_];
__device__ __nv_bfloat16 g_WOlo[(size_t)D_ * D_];
__device__ __nv_bfloat16 g_Qhi[(size_t)M_ * D_];   // projection outputs
__device__ __nv_bfloat16 g_Qlo[(size_t)M_ * D_];
__device__ __nv_bfloat16 g_Khi[(size_t)M_ * D_];
__device__ __nv_bfloat16 g_Klo[(size_t)M_ * D_];
__device__ __nv_bfloat16 g_Vhi[(size_t)M_ * D_];
__device__ __nv_bfloat16 g_Vlo[(size_t)M_ * D_];

// ---------------------------------------------------------------------------
// Helpers (base-target PTX only: ldmatrix / mma.sync / cp.async)
// ---------------------------------------------------------------------------
__device__ __forceinline__ uint32_t smem_to_u32(const void* p) {
    uint32_t a;
    asm("{ .reg .u64 t; cvta.to.shared.u64 t, %1; cvt.u32.u64 %0, t; }"
        : "=r"(a) : "l"(p));
    return a;
}
__device__ __forceinline__ void ldsm_x4(uint32_t* r, uint32_t addr) {
    asm volatile("ldmatrix.sync.aligned.m8n8.x4.shared.b16 {%0,%1,%2,%3}, [%4];"
        : "=r"(r[0]), "=r"(r[1]), "=r"(r[2]), "=r"(r[3]) : "r"(addr));
}
__device__ __forceinline__ void ldsm_x4_t(uint32_t* r, uint32_t addr) {
    asm volatile("ldmatrix.sync.aligned.m8n8.x4.trans.shared.b16 {%0,%1,%2,%3}, [%4];"
        : "=r"(r[0]), "=r"(r[1]), "=r"(r[2]), "=r"(r[3]) : "r"(addr));
}
__device__ __forceinline__ void mma_bf16(float* c, const uint32_t* a,
                                         uint32_t b0, uint32_t b1) {
    asm volatile(
        "mma.sync.aligned.m16n8k16.row.col.f32.bf16.bf16.f32 "
        "{%0,%1,%2,%3}, {%4,%5,%6,%7}, {%8,%9}, {%0,%1,%2,%3};"
        : "+f"(c[0]), "+f"(c[1]), "+f"(c[2]), "+f"(c[3])
        : "r"(a[0]), "r"(a[1]), "r"(a[2]), "r"(a[3]), "r"(b0), "r"(b1));
}
__device__ __forceinline__ void cp16(uint32_t dst, const void* src) {
    asm volatile("cp.async.cg.shared.global [%0], [%1], 16;\n" :: "r"(dst), "l"(src));
}
__device__ __forceinline__ void cp_commit() {
    asm volatile("cp.async.commit_group;\n" ::: "memory");
}
__device__ __forceinline__ float ex2f(float x) {
    float r;
    asm("ex2.approx.f32 %0, %1;" : "=f"(r) : "f"(x));
    return r;
}
__device__ __forceinline__ void pk_split2(float a, float b,
                                          uint32_t& hi, uint32_t& lo) {
    __nv_bfloat16 ha = __float2bfloat16(a), hb = __float2bfloat16(b);
    __nv_bfloat162 th = __halves2bfloat162(ha, hb);
    __nv_bfloat162 tl = __halves2bfloat162(
        __float2bfloat16(a - __bfloat162float(ha)),
        __float2bfloat16(b - __bfloat162float(hb)));
    hi = *reinterpret_cast<uint32_t*>(&th);
    lo = *reinterpret_cast<uint32_t*>(&tl);
}
// ldmatrix x4 offset for 128B-row, 8-chunk XOR-swizzled tiles (attn)
__device__ __forceinline__ uint32_t ldsm_off128(int row0, int ch0, int lane) {
    int row = row0 + (lane & 7) + ((lane >> 3) & 1) * 8;
    int ch  = ch0 + (lane >> 4);
    return (uint32_t)(row * 128) + (uint32_t)(((ch ^ (row & 7)) & 7) << 4);
}
// ldmatrix x4 offset for 64B-row, 4-chunk XOR-swizzled tiles (gemm, BK=32)
__device__ __forceinline__ uint32_t ldsm_off64(int row0, int kc, int lane) {
    int row = row0 + (lane & 7) + ((lane >> 3) & 1) * 8;
    int ch  = kc * 2 + (lane >> 4);
    return (uint32_t)(row * 64) + (uint32_t)(((ch ^ ((row >> 1) & 3)) & 3) << 4);
}

// ---------------------------------------------------------------------------
// Fused input-split (3 tensors) and weight transpose-split (4 weights)
// ---------------------------------------------------------------------------
struct SP3 { const float* x[3]; __nv_bfloat16* hi[3]; __nv_bfloat16* lo[3]; };
struct TS4 { const float* w[4]; __nv_bfloat16* hi[4]; __nv_bfloat16* lo[4]; };

__global__ void split3_kernel(SP3 p, int n4)
{
    int i = blockIdx.x * blockDim.x + threadIdx.x;
    if (i >= n4) return;
    const int z = blockIdx.z;
    float4 v = ((const float4*)p.x[z])[i];
    __nv_bfloat16 h0 = __float2bfloat16(v.x), h1 = __float2bfloat16(v.y);
    __nv_bfloat16 h2 = __float2bfloat16(v.z), h3 = __float2bfloat16(v.w);
    __nv_bfloat16 l0 = __float2bfloat16(v.x - __bfloat162float(h0));
    __nv_bfloat16 l1 = __float2bfloat16(v.y - __bfloat162float(h1));
    __nv_bfloat16 l2 = __float2bfloat16(v.z - __bfloat162float(h2));
    __nv_bfloat16 l3 = __float2bfloat16(v.w - __bfloat162float(h3));
    __nv_bfloat162* hp = (__nv_bfloat162*)(p.hi[z] + (size_t)i * 4);
    __nv_bfloat162* lp = (__nv_bfloat162*)(p.lo[z] + (size_t)i * 4);
    hp[0] = __halves2bfloat162(h0, h1); hp[1] = __halves2bfloat162(h2, h3);
    lp[0] = __halves2bfloat162(l0, l1); lp[1] = __halves2bfloat162(l2, l3);
}

__global__ void transpose_split4_kernel(TS4 p)
{
    __shared__ float t[32][33];
    const int z = blockIdx.z;
    const float* w = p.w[z];
    int tx = threadIdx.x, ty = threadIdx.y;
    int bx = blockIdx.x * 32, by = blockIdx.y * 32;
#pragma unroll
    for (int i = 0; i < 4; i++)
        t[ty + i * 8][tx] = w[(size_t)(by + ty + i * 8) * D_ + bx + tx];
    __syncthreads();
#pragma unroll
    for (int i = 0; i < 4; i++) {
        float v = t[tx][ty + i * 8];
        __nv_bfloat16 h = __float2bfloat16(v);
        __nv_bfloat16 l = __float2bfloat16(v - __bfloat162float(h));
        size_t o = (size_t)(bx + ty + i * 8) * D_ + by + tx;
        p.hi[z][o] = h; p.lo[z][o] = l;
    }
}

// ---------------------------------------------------------------------------
// HMMA bf16-split GEMM, BK=32, 4-stage cp.async pipeline, batched over z.
// 128x128 tile, 8 warps (2x4), 64B-row XOR-swizzled smem.
// ---------------------------------------------------------------------------
#define BK_        32
#define G_AH       0
#define G_AL       8192
#define G_BH       16384
#define G_BL       24576
#define G_STAGE    32768
#define G_NBUF     4
#define GSMEM      (G_NBUF * G_STAGE)     // 131072
#define NSTAGES    (D_ / BK_)             // 32

struct GArgs {
    const __nv_bfloat16 *Ah, *Al, *Bh, *Bl;
    const float* bias;
    float* Cf;
    __nv_bfloat16 *Chi, *Clo;
};
struct GBatch { GArgs g[3]; };

__device__ __forceinline__ void g_load_stage(uint32_t sb, const GArgs& a,
                                             int m0, int n0, int kt, int tid)
{
    const int row = tid >> 1;            // 0..127
    const int c0  = (tid & 1) * 2;       // chunk base 0 or 2
    const int swr = (row >> 1) & 3;
    const uint32_t rowoff = (uint32_t)row * 64;
    const size_t ga = (size_t)(m0 + row) * D_ + kt;
    const size_t gb = (size_t)(n0 + row) * D_ + kt;
#pragma unroll
    for (int cc = 0; cc < 2; cc++) {
        int c = c0 + cc;
        uint32_t so = rowoff + (uint32_t)((c ^ swr) << 4);
        cp16(sb + G_AH + so, a.Ah + ga + c * 8);
        cp16(sb + G_AL + so, a.Al + ga + c * 8);
        cp16(sb + G_BH + so, a.Bh + gb + c * 8);
        cp16(sb + G_BL + so, a.Bl + gb + c * 8);
    }
}

__global__ __launch_bounds__(256, 1)
void gemm_hmma(GBatch batch)
{
    extern __shared__ char smem[];
    const uint32_t su = smem_to_u32(smem);
    const GArgs a = batch.g[blockIdx.z];
    const int tid = threadIdx.x, lane = tid & 31;
    const int m0 = blockIdx.y * 128, n0 = blockIdx.x * 128;
    const int warpM = (tid >> 5) & 1;     // 64 rows each
    const int warpN = tid >> 6;           // 32 cols each

    // precomputed ldsm offsets: A rows (4 i x 2 kc), B rows (2 j x 2 kc)
    uint32_t aoff[2][4], boff[2][2];
#pragma unroll
    for (int kc = 0; kc < 2; kc++) {
#pragma unroll
        for (int i = 0; i < 4; i++)
            aoff[kc][i] = ldsm_off64(warpM * 64 + i * 16, kc, lane);
#pragma unroll
        for (int j = 0; j < 2; j++)
            boff[kc][j] = ldsm_off64(warpN * 32 + j * 16, kc, lane);
    }

    float acc[4][4][4];
#pragma unroll
    for (int i = 0; i < 4; i++)
#pragma unroll
        for (int j = 0; j < 4; j++)
#pragma unroll
            for (int r = 0; r < 4; r++) acc[i][j][r] = 0.0f;

#pragma unroll
    for (int s = 0; s < G_NBUF; s++) {
        g_load_stage(su + s * G_STAGE, a, m0, n0, s * BK_, tid);
        cp_commit();
    }

    for (int c = 0; c < NSTAGES; c++) {
        asm volatile("cp.async.wait_group 3;\n" ::: "memory");
        __syncthreads();

        const uint32_t sb = su + (uint32_t)(c & (G_NBUF - 1)) * G_STAGE;
#pragma unroll
        for (int kc = 0; kc < 2; kc++) {
            uint32_t ah[4][4], al[4][4], bh[2][4], bl[2][4];
#pragma unroll
            for (int i = 0; i < 4; i++) {
                ldsm_x4(ah[i], sb + G_AH + aoff[kc][i]);
                ldsm_x4(al[i], sb + G_AL + aoff[kc][i]);
            }
#pragma unroll
            for (int j = 0; j < 2; j++) {
                ldsm_x4(bh[j], sb + G_BH + boff[kc][j]);
                ldsm_x4(bl[j], sb + G_BL + boff[kc][j]);
            }
#pragma unroll
            for (int i = 0; i < 4; i++)
#pragma unroll
                for (int j = 0; j < 4; j++) {
                    const int g = j >> 1, p = j & 1;
                    mma_bf16(acc[i][j], ah[i], bh[g][p], bh[g][p + 2]);
                    mma_bf16(acc[i][j], ah[i], bl[g][p], bl[g][p + 2]);
                    mma_bf16(acc[i][j], al[i], bh[g][p], bh[g][p + 2]);
                }
        }
        __syncthreads();
        if (c + G_NBUF < NSTAGES)
            g_load_stage(sb, a, m0, n0, (c + G_NBUF) * BK_, tid);
        cp_commit();   // always commit so wait_group 3 stays uniform
    }

    const int crow = lane >> 2, ccol = (lane & 3) * 2;
#pragma unroll
    for (int i = 0; i < 4; i++) {
        const int gr = m0 + warpM * 64 + i * 16 + crow;
#pragma unroll
        for (int j = 0; j < 4; j++) {
            const int gc = n0 + warpN * 32 + j * 8 + ccol;
            const float b0 = __ldg(a.bias + gc), b1 = __ldg(a.bias + gc + 1);
            float v0 = acc[i][j][0] + b0, v1 = acc[i][j][1] + b1;
            float v2 = acc[i][j][2] + b0, v3 = acc[i][j][3] + b1;
            if (a.Cf) {
                *(float2*)(a.Cf + (size_t)gr * D_ + gc)       = make_float2(v0, v1);
                *(float2*)(a.Cf + (size_t)(gr + 8) * D_ + gc) = make_float2(v2, v3);
            } else {
                uint32_t h01, l01, h23, l23;
                pk_split2(v0, v1, h01, l01);
                pk_split2(v2, v3, h23, l23);
                *(uint32_t*)(a.Chi + (size_t)gr * D_ + gc)       = h01;
                *(uint32_t*)(a.Chi + (size_t)(gr + 8) * D_ + gc) = h23;
                *(uint32_t*)(a.Clo + (size_t)gr * D_ + gc)       = l01;
                *(uint32_t*)(a.Clo + (size_t)(gr + 8) * D_ + gc) = l23;
            }
        }
    }
}

// ---------------------------------------------------------------------------
// HMMA flash attention. CTA: 64 q-rows, 4 warps, 2 CTAs/SM.
// kv tile 64, double buffer. QK^T and PV both 3-term bf16 splits.
// log2-domain softmax (ex2.approx). Precomputed ldsm offsets.
// smem: Q 16KB + 2 stages x 32KB = 80KB.
// ---------------------------------------------------------------------------
#define ATT_STAGE  32768
#define ATT_SMEM   (16384 + 2 * ATT_STAGE)   // 81920
#define NKV        (S_ / 64)                  // 32

__device__ __forceinline__ void att_load_kv(uint32_t stg_base,
    const __nv_bfloat16* __restrict__ Khi, const __nv_bfloat16* __restrict__ Klo,
    const __nv_bfloat16* __restrict__ Vhi, const __nv_bfloat16* __restrict__ Vlo,
    size_t rowbase, int jt, int col0, int tid)
{
#pragma unroll
    for (int i = 0; i < 4; i++) {
        int c = tid + i * 128;             // 0..511
        int r = c >> 3, ch = c & 7;
        uint32_t so = (uint32_t)(r * 128 + (((ch ^ (r & 7)) & 7) << 4));
        const size_t g = (rowbase + jt + r) * D_ + col0 + ch * 8;
        cp16(stg_base + 0     + so, Khi + g);
        cp16(stg_base + 8192  + so, Klo + g);
        cp16(stg_base + 16384 + so, Vhi + g);
        cp16(stg_base + 24576 + so, Vlo + g);
    }
}

__global__ __launch_bounds__(128, 2)
void attn_hmma(const __nv_bfloat16* __restrict__ Qhi, const __nv_bfloat16* __restrict__ Qlo,
               const __nv_bfloat16* __restrict__ Khi, const __nv_bfloat16* __restrict__ Klo,
               const __nv_bfloat16* __restrict__ Vhi, const __nv_bfloat16* __restrict__ Vlo,
               __nv_bfloat16* __restrict__ Ohi, __nv_bfloat16* __restrict__ Olo)
{
    extern __shared__ char smem[];
    const uint32_t su = smem_to_u32(smem);
    const int tid = threadIdx.x, lane = tid & 31, warp = tid >> 5;
    const int q0 = blockIdx.x * 64;
    const int h  = blockIdx.y, b = blockIdx.z;
    const size_t rowbase = (size_t)b * S_;
    const int col0 = h * DK_;

    const uint32_t QHI = su, QLO = su + 8192;
    const uint32_t STG = su + 16384;

    // precomputed ldsm offsets: soff[r16][c2] for row0=r*16, ch0=c*2
    uint32_t soff[4][4];
#pragma unroll
    for (int r = 0; r < 4; r++)
#pragma unroll
        for (int c = 0; c < 4; c++)
            soff[r][c] = ldsm_off128(r * 16, c * 2, lane);

#pragma unroll
    for (int i = 0; i < 4; i++) {
        int c = tid + i * 128;             // 0..511
        int r = c >> 3, ch = c & 7;
        uint32_t so = (uint32_t)(r * 128 + (((ch ^ (r & 7)) & 7) << 4));
        const size_t g = (rowbase + q0 + r) * D_ + col0 + ch * 8;
        cp16(QHI + so, Qhi + g);
        cp16(QLO + so, Qlo + g);
    }
    cp_commit();
    att_load_kv(STG, Khi, Klo, Vhi, Vlo, rowbase, 0, col0, tid);
    cp_commit();
    att_load_kv(STG + ATT_STAGE, Khi, Klo, Vhi, Vlo, rowbase, 64, col0, tid);
    cp_commit();

    asm volatile("cp.async.wait_group 2;\n" ::: "memory");
    __syncthreads();

    uint32_t qh[4][4], ql[4][4];
#pragma unroll
    for (int kc = 0; kc < 4; kc++) {
        ldsm_x4(qh[kc], QHI + soff[warp][kc]);
        ldsm_x4(ql[kc], QLO + soff[warp][kc]);
    }

    float oacc[8][4];
#pragma unroll
    for (int j = 0; j < 8; j++)
#pragma unroll
        for (int i = 0; i < 4; i++) oacc[j][i] = 0.0f;
    float m0 = -3.0e38f, m1 = -3.0e38f, l0 = 0.0f, l1 = 0.0f;
    const float SCALE = 0.125f * 1.4426950408889634f;  // /sqrt(64) * log2(e)

    for (int c = 0; c < NKV; c++) {
        if (c < NKV - 1)
            asm volatile("cp.async.wait_group 1;\n" ::: "memory");
        else
            asm volatile("cp.async.wait_group 0;\n" ::: "memory");
        __syncthreads();

        const uint32_t KB = STG + (uint32_t)(c & 1) * ATT_STAGE;
        const uint32_t KBL = KB + 8192, VBH = KB + 16384, VBL = KB + 24576;

        // ---- S = Q @ K^T  (3-term split), S tile [16 q, 64 kv] per warp
        float sacc[8][4];
#pragma unroll
        for (int j = 0; j < 8; j++)
#pragma unroll
            for (int i = 0; i < 4; i++) sacc[j][i] = 0.0f;

#pragma unroll
        for (int kc = 0; kc < 4; kc++) {
            uint32_t kh[4][4], kl[4][4];
#pragma unroll
            for (int ng = 0; ng < 4; ng++) {
                ldsm_x4(kh[ng], KB  + soff[ng][kc]);
                ldsm_x4(kl[ng], KBL + soff[ng][kc]);
            }
#pragma unroll
            for (int j = 0; j < 8; j++) {
                const int g = j >> 1, p = j & 1;
                mma_bf16(sacc[j], qh[kc], kh[g][p], kh[g][p + 2]);
                mma_bf16(sacc[j], qh[kc], kl[g][p], kl[g][p + 2]);
                mma_bf16(sacc[j], ql[kc], kh[g][p], kh[g][p + 2]);
            }
        }

        // ---- online softmax in log2 domain (rows lane>>2 and +8)
#pragma unroll
        for (int j = 0; j < 8; j++)
#pragma unroll
            for (int i = 0; i < 4; i++) sacc[j][i] *= SCALE;

        float mx0 = -3.0e38f, mx1 = -3.0e38f;
#pragma unroll
        for (int j = 0; j < 8; j++) {
            mx0 = fmaxf(mx0, fmaxf(sacc[j][0], sacc[j][1]));
            mx1 = fmaxf(mx1, fmaxf(sacc[j][2], sacc[j][3]));
        }
        mx0 = fmaxf(mx0, __shfl_xor_sync(0xffffffffu, mx0, 1));
        mx0 = fmaxf(mx0, __shfl_xor_sync(0xffffffffu, mx0, 2));
        mx1 = fmaxf(mx1, __shfl_xor_sync(0xffffffffu, mx1, 1));
        mx1 = fmaxf(mx1, __shfl_xor_sync(0xffffffffu, mx1, 2));

        float mn0 = fmaxf(m0, mx0), mn1 = fmaxf(m1, mx1);
        float corr0 = ex2f(m0 - mn0), corr1 = ex2f(m1 - mn1);
        m0 = mn0; m1 = mn1;

        float s0 = 0.0f, s1 = 0.0f;
#pragma unroll
        for (int j = 0; j < 8; j++) {
            sacc[j][0] = ex2f(sacc[j][0] - mn0);
            sacc[j][1] = ex2f(sacc[j][1] - mn0);
            sacc[j][2] = ex2f(sacc[j][2] - mn1);
            sacc[j][3] = ex2f(sacc[j][3] - mn1);
            s0 += sacc[j][0] + sacc[j][1];
            s1 += sacc[j][2] + sacc[j][3];
        }
        s0 += __shfl_xor_sync(0xffffffffu, s0, 1);
        s0 += __shfl_xor_sync(0xffffffffu, s0, 2);
        s1 += __shfl_xor_sync(0xffffffffu, s1, 1);
        s1 += __shfl_xor_sync(0xffffffffu, s1, 2);
        l0 = l0 * corr0 + s0;
        l1 = l1 * corr1 + s1;

#pragma unroll
        for (int j = 0; j < 8; j++) {
            oacc[j][0] *= corr0; oacc[j][1] *= corr0;
            oacc[j][2] *= corr1; oacc[j][3] *= corr1;
        }

        // ---- O += (Phi+Plo) @ (Vhi+Vlo) minus Plo*Vlo cross term
#pragma unroll
        for (int kc = 0; kc < 4; kc++) {
            uint32_t ph[4], pl[4];
            pk_split2(sacc[2 * kc][0],     sacc[2 * kc][1],     ph[0], pl[0]);
            pk_split2(sacc[2 * kc][2],     sacc[2 * kc][3],     ph[1], pl[1]);
            pk_split2(sacc[2 * kc + 1][0], sacc[2 * kc + 1][1], ph[2], pl[2]);
            pk_split2(sacc[2 * kc + 1][2], sacc[2 * kc + 1][3], ph[3], pl[3]);
#pragma unroll
            for (int dg = 0; dg < 4; dg++) {
                uint32_t vh[4], vl[4];
                ldsm_x4_t(vh, VBH + soff[kc][dg]);
                ldsm_x4_t(vl, VBL + soff[kc][dg]);
                mma_bf16(oacc[2 * dg],     ph, vh[0], vh[1]);
                mma_bf16(oacc[2 * dg + 1], ph, vh[2], vh[3]);
                mma_bf16(oacc[2 * dg],     ph, vl[0], vl[1]);
                mma_bf16(oacc[2 * dg + 1], ph, vl[2], vl[3]);
                mma_bf16(oacc[2 * dg],     pl, vh[0], vh[1]);
                mma_bf16(oacc[2 * dg + 1], pl, vh[2], vh[3]);
            }
        }

        __syncthreads();
        if (c + 2 < NKV) {
            att_load_kv(STG + (uint32_t)(c & 1) * ATT_STAGE,
                        Khi, Klo, Vhi, Vlo, rowbase, (c + 2) * 64, col0, tid);
            cp_commit();
        }
    }

    // ---- epilogue: normalize, split to bf16 hi/lo, store
    const float inv0 = 1.0f / l0, inv1 = 1.0f / l1;
    const int r0 = warp * 16 + (lane >> 2);
    const int c0 = (lane & 3) * 2;
#pragma unroll
    for (int j = 0; j < 8; j++) {
        const int dcol = col0 + j * 8 + c0;
        const size_t o0 = (rowbase + q0 + r0) * D_ + dcol;
        const size_t o1 = (rowbase + q0 + r0 + 8) * D_ + dcol;
        uint32_t h01, l01, h23, l23;
        pk_split2(oacc[j][0] * inv0, oacc[j][1] * inv0, h01, l01);
        pk_split2(oacc[j][2] * inv1, oacc[j][3] * inv1, h23, l23);
        *(uint32_t*)(Ohi + o0) = h01;
        *(uint32_t*)(Ohi + o1) = h23;
        *(uint32_t*)(Olo + o0) = l01;
        *(uint32_t*)(Olo + o1) = l23;
    }
}

// ---------------------------------------------------------------------------
// kernel_launch: 5 launches total
// ---------------------------------------------------------------------------
extern "C" void kernel_launch(void* const* d_in, const int* in_sizes, int n_in,
                              void* d_out, int out_size)
{
    const float* q  = (const float*)d_in[0];
    const float* k  = (const float*)d_in[1];
    const float* v  = (const float*)d_in[2];
    const float* wq = (const float*)d_in[3];
    const float* bq = (const float*)d_in[4];
    const float* wk = (const float*)d_in[5];
    const float* bk = (const float*)d_in[6];
    const float* wv = (const float*)d_in[7];
    const float* bv = (const float*)d_in[8];
    const float* wo = (const float*)d_in[9];
    const float* bo = (const float*)d_in[10];
    float* out = (float*)d_out;

    __nv_bfloat16 *Xqh, *Xql, *Xkh, *Xkl, *Xvh, *Xvl;
    __nv_bfloat16 *WQh, *WQl, *WKh, *WKl, *WVh, *WVl, *WOh, *WOl;
    __nv_bfloat16 *Qh, *Ql, *Kh, *Kl, *Vh, *Vl;
    cudaGetSymbolAddress((void**)&Xqh, g_Xqhi);
    cudaGetSymbolAddress((void**)&Xql, g_Xqlo);
    cudaGetSymbolAddress((void**)&Xkh, g_Xkhi);
    cudaGetSymbolAddress((void**)&Xkl, g_Xklo);
    cudaGetSymbolAddress((void**)&Xvh, g_Xvhi);
    cudaGetSymbolAddress((void**)&Xvl, g_Xvlo);
    cudaGetSymbolAddress((void**)&WQh, g_WQhi);
    cudaGetSymbolAddress((void**)&WQl, g_WQlo);
    cudaGetSymbolAddress((void**)&WKh, g_WKhi);
    cudaGetSymbolAddress((void**)&WKl, g_WKlo);
    cudaGetSymbolAddress((void**)&WVh, g_WVhi);
    cudaGetSymbolAddress((void**)&WVl, g_WVlo);
    cudaGetSymbolAddress((void**)&WOh, g_WOhi);
    cudaGetSymbolAddress((void**)&WOl, g_WOlo);
    cudaGetSymbolAddress((void**)&Qh, g_Qhi);
    cudaGetSymbolAddress((void**)&Ql, g_Qlo);
    cudaGetSymbolAddress((void**)&Kh, g_Khi);
    cudaGetSymbolAddress((void**)&Kl, g_Klo);
    cudaGetSymbolAddress((void**)&Vh, g_Vhi);
    cudaGetSymbolAddress((void**)&Vl, g_Vlo);

    cudaFuncSetAttribute(gemm_hmma,
                         cudaFuncAttributeMaxDynamicSharedMemorySize, GSMEM);
    cudaFuncSetAttribute(attn_hmma,
                         cudaFuncAttributeMaxDynamicSharedMemorySize, ATT_SMEM);

    // 1) all weight transposes
    TS4 ts = {{wq, wk, wv, wo}, {WQh, WKh, WVh, WOh}, {WQl, WKl, WVl, WOl}};
    transpose_split4_kernel<<<dim3(D_ / 32, D_ / 32, 4), dim3(32, 8)>>>(ts);

    // 2) all input splits
    const int n4 = M_ * D_ / 4;
    SP3 sp = {{q, k, v}, {Xqh, Xkh, Xvh}, {Xql, Xkl, Xvl}};
    split3_kernel<<<dim3(n4 / 256, 1, 3), 256>>>(sp, n4);

    // 3) batched Q/K/V projections (bf16 hi/lo out)
    GBatch pb;
    pb.g[0] = {Xqh, Xql, WQh, WQl, bq, nullptr, Qh, Ql};
    pb.g[1] = {Xkh, Xkl, WKh, WKl, bk, nullptr, Kh, Kl};
    pb.g[2] = {Xvh, Xvl, WVh, WVl, bv, nullptr, Vh, Vl};
    gemm_hmma<<<dim3(D_ / 128, M_ / 128, 3), 256, GSMEM>>>(pb);

    // 4) attention -> O split into Xq buffers (done with their input role)
    attn_hmma<<<dim3(S_ / 64, H_, B_), 128, ATT_SMEM>>>(
        Qh, Ql, Kh, Kl, Vh, Vl, Xqh, Xql);

    // 5) output projection -> fp32 out
    GBatch ob;
    ob.g[0] = {Xqh, Xql, WOh, WOl, bo, out, nullptr, nullptr};
    ob.g[1] = ob.g[0];
    ob.g[2] = ob.g[0];
    gemm_hmma<<<dim3(D_ / 128, M_ / 128, 1), 256, GSMEM>>>(ob);
}

// round 8
// speedup vs baseline: 1.7591x; 1.7591x over previous
#include <cuda_runtime.h>
#include <cuda_bf16.h>
#include <cstdint>

// Problem constants
#define B_   4
#define S_   2048
#define D_   1024
#define H_   16
#define DK_  64
#define M_   (B_ * S_)   // 8192

// ---------------------------------------------------------------------------
// Scratch (device globals — no allocations allowed)
// ---------------------------------------------------------------------------
__device__ __nv_bfloat16 g_Xqhi[(size_t)M_ * D_];  // input splits; Xq reused for O
__device__ __nv_bfloat16 g_Xqlo[(size_t)M_ * D_];
__device__ __nv_bfloat16 g_Xkhi[(size_t)M_ * D_];
__device__ __nv_bfloat16 g_Xklo[(size_t)M_ * D_];
__device__ __nv_bfloat16 g_Xvhi[(size_t)M_ * D_];
__device__ __nv_bfloat16 g_Xvlo[(size_t)M_ * D_];
__device__ __nv_bfloat16 g_WQhi[(size_t)D_ * D_];  // transposed weights [N,K]
__device__ __nv_bfloat16 g_WQlo[(size_t)D_ * D_];
__device__ __nv_bfloat16 g_WKhi[(size_t)D_ * D_];
__device__ __nv_bfloat16 g_WKlo[(size_t)D_ * D_];
__device__ __nv_bfloat16 g_WVhi[(size_t)D_ * D_];
__device__ __nv_bfloat16 g_WVlo[(size_t)D_ * D_];
__device__ __nv_bfloat16 g_WOhi[(size_t)D_ * D_];
__device__ __nv_bfloat16 g_WOlo[(size_t)D_ * D_];
__device__ __nv_bfloat16 g_Qhi[(size_t)M_ * D_];   // projection outputs
__device__ __nv_bfloat16 g_Qlo[(size_t)M_ * D_];
__device__ __nv_bfloat16 g_Khi[(size_t)M_ * D_];
__device__ __nv_bfloat16 g_Klo[(size_t)M_ * D_];
__device__ __nv_bfloat16 g_Vhi[(size_t)M_ * D_];
__device__ __nv_bfloat16 g_Vlo[(size_t)M_ * D_];

// ---------------------------------------------------------------------------
// Helpers (base-target PTX only: ldmatrix / mma.sync / cp.async)
// ---------------------------------------------------------------------------
__device__ __forceinline__ uint32_t smem_to_u32(const void* p) {
    uint32_t a;
    asm("{ .reg .u64 t; cvta.to.shared.u64 t, %1; cvt.u32.u64 %0, t; }"
        : "=r"(a) : "l"(p));
    return a;
}
__device__ __forceinline__ void ldsm_x4(uint32_t* r, uint32_t addr) {
    asm volatile("ldmatrix.sync.aligned.m8n8.x4.shared.b16 {%0,%1,%2,%3}, [%4];"
        : "=r"(r[0]), "=r"(r[1]), "=r"(r[2]), "=r"(r[3]) : "r"(addr));
}
__device__ __forceinline__ void ldsm_x4_t(uint32_t* r, uint32_t addr) {
    asm volatile("ldmatrix.sync.aligned.m8n8.x4.trans.shared.b16 {%0,%1,%2,%3}, [%4];"
        : "=r"(r[0]), "=r"(r[1]), "=r"(r[2]), "=r"(r[3]) : "r"(addr));
}
__device__ __forceinline__ void mma_bf16(float* c, const uint32_t* a,
                                         uint32_t b0, uint32_t b1) {
    asm volatile(
        "mma.sync.aligned.m16n8k16.row.col.f32.bf16.bf16.f32 "
        "{%0,%1,%2,%3}, {%4,%5,%6,%7}, {%8,%9}, {%0,%1,%2,%3};"
        : "+f"(c[0]), "+f"(c[1]), "+f"(c[2]), "+f"(c[3])
        : "r"(a[0]), "r"(a[1]), "r"(a[2]), "r"(a[3]), "r"(b0), "r"(b1));
}
__device__ __forceinline__ void cp16(uint32_t dst, const void* src) {
    asm volatile("cp.async.cg.shared.global [%0], [%1], 16;\n" :: "r"(dst), "l"(src));
}
__device__ __forceinline__ void cp_commit() {
    asm volatile("cp.async.commit_group;\n" ::: "memory");
}
__device__ __forceinline__ void pk_split2(float a, float b,
                                          uint32_t& hi, uint32_t& lo) {
    __nv_bfloat16 ha = __float2bfloat16(a), hb = __float2bfloat16(b);
    __nv_bfloat162 th = __halves2bfloat162(ha, hb);
    __nv_bfloat162 tl = __halves2bfloat162(
        __float2bfloat16(a - __bfloat162float(ha)),
        __float2bfloat16(b - __bfloat162float(hb)));
    hi = *reinterpret_cast<uint32_t*>(&th);
    lo = *reinterpret_cast<uint32_t*>(&tl);
}
// ldmatrix x4 address for 128B-row, 8-chunk XOR-swizzled tiles
__device__ __forceinline__ uint32_t ldsm_addr(uint32_t base, int row0, int ch0, int lane) {
    int row = row0 + (lane & 7) + ((lane >> 3) & 1) * 8;
    int ch  = ch0 + (lane >> 4);
    return base + (uint32_t)(row * 128) + (uint32_t)(((ch ^ (row & 7)) & 7) << 4);
}

// ---------------------------------------------------------------------------
// Fused input-split (3 tensors) and weight transpose-split (4 weights)
// ---------------------------------------------------------------------------
struct SP3 { const float* x[3]; __nv_bfloat16* hi[3]; __nv_bfloat16* lo[3]; };
struct TS4 { const float* w[4]; __nv_bfloat16* hi[4]; __nv_bfloat16* lo[4]; };

__global__ void split3_kernel(SP3 p, int n4)
{
    int i = blockIdx.x * blockDim.x + threadIdx.x;
    if (i >= n4) return;
    const int z = blockIdx.z;
    float4 v = ((const float4*)p.x[z])[i];
    __nv_bfloat16 h0 = __float2bfloat16(v.x), h1 = __float2bfloat16(v.y);
    __nv_bfloat16 h2 = __float2bfloat16(v.z), h3 = __float2bfloat16(v.w);
    __nv_bfloat16 l0 = __float2bfloat16(v.x - __bfloat162float(h0));
    __nv_bfloat16 l1 = __float2bfloat16(v.y - __bfloat162float(h1));
    __nv_bfloat16 l2 = __float2bfloat16(v.z - __bfloat162float(h2));
    __nv_bfloat16 l3 = __float2bfloat16(v.w - __bfloat162float(h3));
    __nv_bfloat162* hp = (__nv_bfloat162*)(p.hi[z] + (size_t)i * 4);
    __nv_bfloat162* lp = (__nv_bfloat162*)(p.lo[z] + (size_t)i * 4);
    hp[0] = __halves2bfloat162(h0, h1); hp[1] = __halves2bfloat162(h2, h3);
    lp[0] = __halves2bfloat162(l0, l1); lp[1] = __halves2bfloat162(l2, l3);
}

__global__ void transpose_split4_kernel(TS4 p)
{
    __shared__ float t[32][33];
    const int z = blockIdx.z;
    const float* w = p.w[z];
    int tx = threadIdx.x, ty = threadIdx.y;
    int bx = blockIdx.x * 32, by = blockIdx.y * 32;
#pragma unroll
    for (int i = 0; i < 4; i++)
        t[ty + i * 8][tx] = w[(size_t)(by + ty + i * 8) * D_ + bx + tx];
    __syncthreads();
#pragma unroll
    for (int i = 0; i < 4; i++) {
        float v = t[tx][ty + i * 8];
        __nv_bfloat16 h = __float2bfloat16(v);
        __nv_bfloat16 l = __float2bfloat16(v - __bfloat162float(h));
        size_t o = (size_t)(bx + ty + i * 8) * D_ + by + tx;
        p.hi[z][o] = h; p.lo[z][o] = l;
    }
}

// ---------------------------------------------------------------------------
// HMMA bf16-split GEMM, BK=64, 3-stage cp.async pipeline, batched over z.
// 128x128 tile, 8 warps (2x4), 128B-row XOR-swizzled smem.
// ---------------------------------------------------------------------------
#define BK_        64
#define G_AH       0
#define G_AL       16384
#define G_BH       32768
#define G_BL       49152
#define G_STAGE    65536
#define G_NBUF     3
#define GSMEM      (G_NBUF * G_STAGE)     // 196608
#define NSTAGES    (D_ / BK_)             // 16

struct GArgs {
    const __nv_bfloat16 *Ah, *Al, *Bh, *Bl;
    const float* bias;
    float* Cf;
    __nv_bfloat16 *Chi, *Clo;
};
struct GBatch { GArgs g[3]; };

__device__ __forceinline__ void g_load_stage(uint32_t sb, const GArgs& a,
                                             int m0, int n0, int kt, int tid)
{
#pragma unroll
    for (int i = 0; i < 4; i++) {
        int c = tid + i * 256;              // 0..1023
        int r = c >> 3, ch = c & 7;
        uint32_t so = (uint32_t)(r * 128 + (((ch ^ (r & 7)) & 7) << 4));
        const size_t ga = (size_t)(m0 + r) * D_ + kt + ch * 8;
        const size_t gb = (size_t)(n0 + r) * D_ + kt + ch * 8;
        cp16(sb + G_AH + so, a.Ah + ga);
        cp16(sb + G_AL + so, a.Al + ga);
        cp16(sb + G_BH + so, a.Bh + gb);
        cp16(sb + G_BL + so, a.Bl + gb);
    }
}

__global__ __launch_bounds__(256, 1)
void gemm_hmma(GBatch batch)
{
    extern __shared__ char smem[];
    const uint32_t su = smem_to_u32(smem);
    const GArgs a = batch.g[blockIdx.z];
    const int tid = threadIdx.x, lane = tid & 31;
    const int m0 = blockIdx.y * 128, n0 = blockIdx.x * 128;
    const int warpM = (tid >> 5) & 1;     // 64 rows each
    const int warpN = tid >> 6;           // 32 cols each

    float acc[4][4][4];
#pragma unroll
    for (int i = 0; i < 4; i++)
#pragma unroll
        for (int j = 0; j < 4; j++)
#pragma unroll
            for (int r = 0; r < 4; r++) acc[i][j][r] = 0.0f;

#pragma unroll
    for (int s = 0; s < G_NBUF; s++) {
        g_load_stage(su + s * G_STAGE, a, m0, n0, s * BK_, tid);
        cp_commit();
    }

    uint32_t sb = su;
    int buf = 0;
    for (int c = 0; c < NSTAGES; c++) {
        asm volatile("cp.async.wait_group 2;\n" ::: "memory");
        __syncthreads();

#pragma unroll
        for (int kc = 0; kc < 4; kc++) {
            uint32_t ah[4][4], al[4][4], bh[2][4], bl[2][4];
#pragma unroll
            for (int i = 0; i < 4; i++) {
                ldsm_x4(ah[i], ldsm_addr(sb + G_AH, warpM * 64 + i * 16, kc * 2, lane));
                ldsm_x4(al[i], ldsm_addr(sb + G_AL, warpM * 64 + i * 16, kc * 2, lane));
            }
#pragma unroll
            for (int j = 0; j < 2; j++) {
                ldsm_x4(bh[j], ldsm_addr(sb + G_BH, warpN * 32 + j * 16, kc * 2, lane));
                ldsm_x4(bl[j], ldsm_addr(sb + G_BL, warpN * 32 + j * 16, kc * 2, lane));
            }
#pragma unroll
            for (int i = 0; i < 4; i++)
#pragma unroll
                for (int j = 0; j < 4; j++) {
                    const int g = j >> 1, p = j & 1;
                    mma_bf16(acc[i][j], ah[i], bh[g][p], bh[g][p + 2]);
                    mma_bf16(acc[i][j], ah[i], bl[g][p], bl[g][p + 2]);
                    mma_bf16(acc[i][j], al[i], bh[g][p], bh[g][p + 2]);
                }
        }
        __syncthreads();
        if (c + G_NBUF < NSTAGES)
            g_load_stage(sb, a, m0, n0, (c + G_NBUF) * BK_, tid);
        cp_commit();   // always commit so wait_group 2 stays uniform

        buf = (buf == G_NBUF - 1) ? 0 : buf + 1;
        sb = su + (uint32_t)buf * G_STAGE;
    }

    const int crow = lane >> 2, ccol = (lane & 3) * 2;
#pragma unroll
    for (int i = 0; i < 4; i++) {
        const int gr = m0 + warpM * 64 + i * 16 + crow;
#pragma unroll
        for (int j = 0; j < 4; j++) {
            const int gc = n0 + warpN * 32 + j * 8 + ccol;
            const float b0 = __ldg(a.bias + gc), b1 = __ldg(a.bias + gc + 1);
            float v0 = acc[i][j][0] + b0, v1 = acc[i][j][1] + b1;
            float v2 = acc[i][j][2] + b0, v3 = acc[i][j][3] + b1;
            if (a.Cf) {
                *(float2*)(a.Cf + (size_t)gr * D_ + gc)       = make_float2(v0, v1);
                *(float2*)(a.Cf + (size_t)(gr + 8) * D_ + gc) = make_float2(v2, v3);
            } else {
                uint32_t h01, l01, h23, l23;
                pk_split2(v0, v1, h01, l01);
                pk_split2(v2, v3, h23, l23);
                *(uint32_t*)(a.Chi + (size_t)gr * D_ + gc)       = h01;
                *(uint32_t*)(a.Chi + (size_t)(gr + 8) * D_ + gc) = h23;
                *(uint32_t*)(a.Clo + (size_t)gr * D_ + gc)       = l01;
                *(uint32_t*)(a.Clo + (size_t)(gr + 8) * D_ + gc) = l23;
            }
        }
    }
}

// ---------------------------------------------------------------------------
// HMMA flash attention (verbatim R6 measured-best).
// CTA: 64 q-rows, 4 warps, 2 CTAs/SM. kv tile 64, double buffer.
// QK^T and PV both 3-term bf16 splits. smem: Q 16KB + 2 x 32KB = 80KB.
// ---------------------------------------------------------------------------
#define ATT_STAGE  32768
#define ATT_SMEM   (16384 + 2 * ATT_STAGE)   // 81920
#define NKV        (S_ / 64)                  // 32

__device__ __forceinline__ void att_load_kv(uint32_t stg_base,
    const __nv_bfloat16* __restrict__ Khi, const __nv_bfloat16* __restrict__ Klo,
    const __nv_bfloat16* __restrict__ Vhi, const __nv_bfloat16* __restrict__ Vlo,
    size_t rowbase, int jt, int col0, int tid)
{
#pragma unroll
    for (int i = 0; i < 4; i++) {
        int c = tid + i * 128;             // 0..511
        int r = c >> 3, ch = c & 7;
        uint32_t so = (uint32_t)(r * 128 + (((ch ^ (r & 7)) & 7) << 4));
        const size_t g = (rowbase + jt + r) * D_ + col0 + ch * 8;
        cp16(stg_base + 0     + so, Khi + g);
        cp16(stg_base + 8192  + so, Klo + g);
        cp16(stg_base + 16384 + so, Vhi + g);
        cp16(stg_base + 24576 + so, Vlo + g);
    }
}

__global__ __launch_bounds__(128, 2)
void attn_hmma(const __nv_bfloat16* __restrict__ Qhi, const __nv_bfloat16* __restrict__ Qlo,
               const __nv_bfloat16* __restrict__ Khi, const __nv_bfloat16* __restrict__ Klo,
               const __nv_bfloat16* __restrict__ Vhi, const __nv_bfloat16* __restrict__ Vlo,
               __nv_bfloat16* __restrict__ Ohi, __nv_bfloat16* __restrict__ Olo)
{
    extern __shared__ char smem[];
    const uint32_t su = smem_to_u32(smem);
    const int tid = threadIdx.x, lane = tid & 31, warp = tid >> 5;
    const int q0 = blockIdx.x * 64;
    const int h  = blockIdx.y, b = blockIdx.z;
    const size_t rowbase = (size_t)b * S_;
    const int col0 = h * DK_;

    const uint32_t QHI = su, QLO = su + 8192;
    const uint32_t STG = su + 16384;

#pragma unroll
    for (int i = 0; i < 4; i++) {
        int c = tid + i * 128;             // 0..511
        int r = c >> 3, ch = c & 7;
        uint32_t so = (uint32_t)(r * 128 + (((ch ^ (r & 7)) & 7) << 4));
        const size_t g = (rowbase + q0 + r) * D_ + col0 + ch * 8;
        cp16(QHI + so, Qhi + g);
        cp16(QLO + so, Qlo + g);
    }
    cp_commit();
    att_load_kv(STG, Khi, Klo, Vhi, Vlo, rowbase, 0, col0, tid);
    cp_commit();
    att_load_kv(STG + ATT_STAGE, Khi, Klo, Vhi, Vlo, rowbase, 64, col0, tid);
    cp_commit();

    asm volatile("cp.async.wait_group 2;\n" ::: "memory");
    __syncthreads();

    uint32_t qh[4][4], ql[4][4];
#pragma unroll
    for (int kc = 0; kc < 4; kc++) {
        ldsm_x4(qh[kc], ldsm_addr(QHI, warp * 16, kc * 2, lane));
        ldsm_x4(ql[kc], ldsm_addr(QLO, warp * 16, kc * 2, lane));
    }

    float oacc[8][4];
#pragma unroll
    for (int j = 0; j < 8; j++)
#pragma unroll
        for (int i = 0; i < 4; i++) oacc[j][i] = 0.0f;
    float m0 = -3.0e38f, m1 = -3.0e38f, l0 = 0.0f, l1 = 0.0f;

    for (int c = 0; c < NKV; c++) {
        if (c < NKV - 1)
            asm volatile("cp.async.wait_group 1;\n" ::: "memory");
        else
            asm volatile("cp.async.wait_group 0;\n" ::: "memory");
        __syncthreads();

        const uint32_t KB = STG + (uint32_t)(c & 1) * ATT_STAGE;

        // ---- S = Q @ K^T  (3-term split), S tile [16 q, 64 kv] per warp
        float sacc[8][4];
#pragma unroll
        for (int j = 0; j < 8; j++)
#pragma unroll
            for (int i = 0; i < 4; i++) sacc[j][i] = 0.0f;

#pragma unroll
        for (int kc = 0; kc < 4; kc++) {
            uint32_t kh[4][4], kl[4][4];
#pragma unroll
            for (int ng = 0; ng < 4; ng++) {
                ldsm_x4(kh[ng], ldsm_addr(KB + 0,    ng * 16, kc * 2, lane));
                ldsm_x4(kl[ng], ldsm_addr(KB + 8192, ng * 16, kc * 2, lane));
            }
#pragma unroll
            for (int j = 0; j < 8; j++) {
                const int g = j >> 1, p = j & 1;
                mma_bf16(sacc[j], qh[kc], kh[g][p], kh[g][p + 2]);
                mma_bf16(sacc[j], qh[kc], kl[g][p], kl[g][p + 2]);
                mma_bf16(sacc[j], ql[kc], kh[g][p], kh[g][p + 2]);
            }
        }

        // ---- online softmax in registers (rows lane>>2 and +8)
#pragma unroll
        for (int j = 0; j < 8; j++)
#pragma unroll
            for (int i = 0; i < 4; i++) sacc[j][i] *= 0.125f;

        float mx0 = -3.0e38f, mx1 = -3.0e38f;
#pragma unroll
        for (int j = 0; j < 8; j++) {
            mx0 = fmaxf(mx0, fmaxf(sacc[j][0], sacc[j][1]));
            mx1 = fmaxf(mx1, fmaxf(sacc[j][2], sacc[j][3]));
        }
        mx0 = fmaxf(mx0, __shfl_xor_sync(0xffffffffu, mx0, 1));
        mx0 = fmaxf(mx0, __shfl_xor_sync(0xffffffffu, mx0, 2));
        mx1 = fmaxf(mx1, __shfl_xor_sync(0xffffffffu, mx1, 1));
        mx1 = fmaxf(mx1, __shfl_xor_sync(0xffffffffu, mx1, 2));

        float mn0 = fmaxf(m0, mx0), mn1 = fmaxf(m1, mx1);
        float corr0 = __expf(m0 - mn0), corr1 = __expf(m1 - mn1);
        m0 = mn0; m1 = mn1;

        float s0 = 0.0f, s1 = 0.0f;
#pragma unroll
        for (int j = 0; j < 8; j++) {
            sacc[j][0] = __expf(sacc[j][0] - mn0);
            sacc[j][1] = __expf(sacc[j][1] - mn0);
            sacc[j][2] = __expf(sacc[j][2] - mn1);
            sacc[j][3] = __expf(sacc[j][3] - mn1);
            s0 += sacc[j][0] + sacc[j][1];
            s1 += sacc[j][2] + sacc[j][3];
        }
        s0 += __shfl_xor_sync(0xffffffffu, s0, 1);
        s0 += __shfl_xor_sync(0xffffffffu, s0, 2);
        s1 += __shfl_xor_sync(0xffffffffu, s1, 1);
        s1 += __shfl_xor_sync(0xffffffffu, s1, 2);
        l0 = l0 * corr0 + s0;
        l1 = l1 * corr1 + s1;

#pragma unroll
        for (int j = 0; j < 8; j++) {
            oacc[j][0] *= corr0; oacc[j][1] *= corr0;
            oacc[j][2] *= corr1; oacc[j][3] *= corr1;
        }

        // ---- O += (Phi+Plo) @ (Vhi+Vlo) minus Plo*Vlo cross term
#pragma unroll
        for (int kc = 0; kc < 4; kc++) {
            uint32_t ph[4], pl[4];
            pk_split2(sacc[2 * kc][0],     sacc[2 * kc][1],     ph[0], pl[0]);
            pk_split2(sacc[2 * kc][2],     sacc[2 * kc][3],     ph[1], pl[1]);
            pk_split2(sacc[2 * kc + 1][0], sacc[2 * kc + 1][1], ph[2], pl[2]);
            pk_split2(sacc[2 * kc + 1][2], sacc[2 * kc + 1][3], ph[3], pl[3]);
#pragma unroll
            for (int dg = 0; dg < 4; dg++) {
                uint32_t vh[4], vl[4];
                ldsm_x4_t(vh, ldsm_addr(KB + 16384, kc * 16, dg * 2, lane));
                ldsm_x4_t(vl, ldsm_addr(KB + 24576, kc * 16, dg * 2, lane));
                mma_bf16(oacc[2 * dg],     ph, vh[0], vh[1]);
                mma_bf16(oacc[2 * dg + 1], ph, vh[2], vh[3]);
                mma_bf16(oacc[2 * dg],     ph, vl[0], vl[1]);
                mma_bf16(oacc[2 * dg + 1], ph, vl[2], vl[3]);
                mma_bf16(oacc[2 * dg],     pl, vh[0], vh[1]);
                mma_bf16(oacc[2 * dg + 1], pl, vh[2], vh[3]);
            }
        }

        __syncthreads();
        if (c + 2 < NKV) {
            att_load_kv(STG + (uint32_t)(c & 1) * ATT_STAGE,
                        Khi, Klo, Vhi, Vlo, rowbase, (c + 2) * 64, col0, tid);
            cp_commit();
        }
    }

    // ---- epilogue: normalize, split to bf16 hi/lo, store
    const float inv0 = 1.0f / l0, inv1 = 1.0f / l1;
    const int r0 = warp * 16 + (lane >> 2);
    const int c0 = (lane & 3) * 2;
#pragma unroll
    for (int j = 0; j < 8; j++) {
        const int dcol = col0 + j * 8 + c0;
        const size_t o0 = (rowbase + q0 + r0) * D_ + dcol;
        const size_t o1 = (rowbase + q0 + r0 + 8) * D_ + dcol;
        uint32_t h01, l01, h23, l23;
        pk_split2(oacc[j][0] * inv0, oacc[j][1] * inv0, h01, l01);
        pk_split2(oacc[j][2] * inv1, oacc[j][3] * inv1, h23, l23);
        *(uint32_t*)(Ohi + o0) = h01;
        *(uint32_t*)(Ohi + o1) = h23;
        *(uint32_t*)(Olo + o0) = l01;
        *(uint32_t*)(Olo + o1) = l23;
    }
}

// ---------------------------------------------------------------------------
// kernel_launch: 5 launches total
// ---------------------------------------------------------------------------
extern "C" void kernel_launch(void* const* d_in, const int* in_sizes, int n_in,
                              void* d_out, int out_size)
{
    const float* q  = (const float*)d_in[0];
    const float* k  = (const float*)d_in[1];
    const float* v  = (const float*)d_in[2];
    const float* wq = (const float*)d_in[3];
    const float* bq = (const float*)d_in[4];
    const float* wk = (const float*)d_in[5];
    const float* bk = (const float*)d_in[6];
    const float* wv = (const float*)d_in[7];
    const float* bv = (const float*)d_in[8];
    const float* wo = (const float*)d_in[9];
    const float* bo = (const float*)d_in[10];
    float* out = (float*)d_out;

    __nv_bfloat16 *Xqh, *Xql, *Xkh, *Xkl, *Xvh, *Xvl;
    __nv_bfloat16 *WQh, *WQl, *WKh, *WKl, *WVh, *WVl, *WOh, *WOl;
    __nv_bfloat16 *Qh, *Ql, *Kh, *Kl, *Vh, *Vl;
    cudaGetSymbolAddress((void**)&Xqh, g_Xqhi);
    cudaGetSymbolAddress((void**)&Xql, g_Xqlo);
    cudaGetSymbolAddress((void**)&Xkh, g_Xkhi);
    cudaGetSymbolAddress((void**)&Xkl, g_Xklo);
    cudaGetSymbolAddress((void**)&Xvh, g_Xvhi);
    cudaGetSymbolAddress((void**)&Xvl, g_Xvlo);
    cudaGetSymbolAddress((void**)&WQh, g_WQhi);
    cudaGetSymbolAddress((void**)&WQl, g_WQlo);
    cudaGetSymbolAddress((void**)&WKh, g_WKhi);
    cudaGetSymbolAddress((void**)&WKl, g_WKlo);
    cudaGetSymbolAddress((void**)&WVh, g_WVhi);
    cudaGetSymbolAddress((void**)&WVl, g_WVlo);
    cudaGetSymbolAddress((void**)&WOh, g_WOhi);
    cudaGetSymbolAddress((void**)&WOl, g_WOlo);
    cudaGetSymbolAddress((void**)&Qh, g_Qhi);
    cudaGetSymbolAddress((void**)&Ql, g_Qlo);
    cudaGetSymbolAddress((void**)&Kh, g_Khi);
    cudaGetSymbolAddress((void**)&Kl, g_Klo);
    cudaGetSymbolAddress((void**)&Vh, g_Vhi);
    cudaGetSymbolAddress((void**)&Vl, g_Vlo);

    cudaFuncSetAttribute(gemm_hmma,
                         cudaFuncAttributeMaxDynamicSharedMemorySize, GSMEM);
    cudaFuncSetAttribute(attn_hmma,
                         cudaFuncAttributeMaxDynamicSharedMemorySize, ATT_SMEM);

    // 1) all weight transposes
    TS4 ts = {{wq, wk, wv, wo}, {WQh, WKh, WVh, WOh}, {WQl, WKl, WVl, WOl}};
    transpose_split4_kernel<<<dim3(D_ / 32, D_ / 32, 4), dim3(32, 8)>>>(ts);

    // 2) all input splits
    const int n4 = M_ * D_ / 4;
    SP3 sp = {{q, k, v}, {Xqh, Xkh, Xvh}, {Xql, Xkl, Xvl}};
    split3_kernel<<<dim3(n4 / 256, 1, 3), 256>>>(sp, n4);

    // 3) batched Q/K/V projections (bf16 hi/lo out)
    GBatch pb;
    pb.g[0] = {Xqh, Xql, WQh, WQl, bq, nullptr, Qh, Ql};
    pb.g[1] = {Xkh, Xkl, WKh, WKl, bk, nullptr, Kh, Kl};
    pb.g[2] = {Xvh, Xvl, WVh, WVl, bv, nullptr, Vh, Vl};
    gemm_hmma<<<dim3(D_ / 128, M_ / 128, 3), 256, GSMEM>>>(pb);

    // 4) attention -> O split into Xq buffers (done with their input role)
    attn_hmma<<<dim3(S_ / 64, H_, B_), 128, ATT_SMEM>>>(
        Qh, Ql, Kh, Kl, Vh, Vl, Xqh, Xql);

    // 5) output projection -> fp32 out
    GBatch ob;
    ob.g[0] = {Xqh, Xql, WOh, WOl, bo, out, nullptr, nullptr};
    ob.g[1] = ob.g[0];
    ob.g[2] = ob.g[0];
    gemm_hmma<<<dim3(D_ / 128, M_ / 128, 1), 256, GSMEM>>>(ob);
}

// round 9
// speedup vs baseline: 2.5198x; 1.4324x over previous
#include <cuda_runtime.h>
#include <cuda_fp16.h>
#include <cstdint>

// Problem constants
#define B_   4
#define S_   2048
#define D_   1024
#define H_   16
#define DK_  64
#define M_   (B_ * S_)   // 8192

// ---------------------------------------------------------------------------
// Scratch (device globals — no allocations allowed)
// ---------------------------------------------------------------------------
__device__ __half g_Xq[(size_t)M_ * D_];   // q input fp16; reused for O after attn
__device__ __half g_Xk[(size_t)M_ * D_];
__device__ __half g_Xv[(size_t)M_ * D_];
__device__ __half g_WQh[(size_t)D_ * D_];  // transposed weights [N,K], pre-scaled x32
__device__ __half g_WQl[(size_t)D_ * D_];
__device__ __half g_WKh[(size_t)D_ * D_];
__device__ __half g_WKl[(size_t)D_ * D_];
__device__ __half g_WVh[(size_t)D_ * D_];
__device__ __half g_WVl[(size_t)D_ * D_];
__device__ __half g_WOh[(size_t)D_ * D_];
__device__ __half g_WOl[(size_t)D_ * D_];
__device__ __half g_Q [(size_t)M_ * D_];   // projection outputs
__device__ __half g_Kh[(size_t)M_ * D_];
__device__ __half g_Kl[(size_t)M_ * D_];
__device__ __half g_V [(size_t)M_ * D_];

// ---------------------------------------------------------------------------
// Helpers (base-target PTX only: ldmatrix / mma.sync / cp.async)
// ---------------------------------------------------------------------------
__device__ __forceinline__ uint32_t smem_to_u32(const void* p) {
    uint32_t a;
    asm("{ .reg .u64 t; cvta.to.shared.u64 t, %1; cvt.u32.u64 %0, t; }"
        : "=r"(a) : "l"(p));
    return a;
}
__device__ __forceinline__ void ldsm_x4(uint32_t* r, uint32_t addr) {
    asm volatile("ldmatrix.sync.aligned.m8n8.x4.shared.b16 {%0,%1,%2,%3}, [%4];"
        : "=r"(r[0]), "=r"(r[1]), "=r"(r[2]), "=r"(r[3]) : "r"(addr));
}
__device__ __forceinline__ void ldsm_x4_t(uint32_t* r, uint32_t addr) {
    asm volatile("ldmatrix.sync.aligned.m8n8.x4.trans.shared.b16 {%0,%1,%2,%3}, [%4];"
        : "=r"(r[0]), "=r"(r[1]), "=r"(r[2]), "=r"(r[3]) : "r"(addr));
}
__device__ __forceinline__ void mma_f16(float* c, const uint32_t* a,
                                        uint32_t b0, uint32_t b1) {
    asm volatile(
        "mma.sync.aligned.m16n8k16.row.col.f32.f16.f16.f32 "
        "{%0,%1,%2,%3}, {%4,%5,%6,%7}, {%8,%9}, {%0,%1,%2,%3};"
        : "+f"(c[0]), "+f"(c[1]), "+f"(c[2]), "+f"(c[3])
        : "r"(a[0]), "r"(a[1]), "r"(a[2]), "r"(a[3]), "r"(b0), "r"(b1));
}
__device__ __forceinline__ void cp16(uint32_t dst, const void* src) {
    asm volatile("cp.async.cg.shared.global [%0], [%1], 16;\n" :: "r"(dst), "l"(src));
}
__device__ __forceinline__ void cp_commit() {
    asm volatile("cp.async.commit_group;\n" ::: "memory");
}
__device__ __forceinline__ uint32_t pk_h2(float a, float b) {
    __half2 t = __floats2half2_rn(a, b);
    return *reinterpret_cast<uint32_t*>(&t);
}
__device__ __forceinline__ void pk_split2h(float a, float b,
                                           uint32_t& hi, uint32_t& lo) {
    __half ha = __float2half_rn(a), hb = __float2half_rn(b);
    __half2 th = __halves2half2(ha, hb);
    __half2 tl = __halves2half2(
        __float2half_rn(a - __half2float(ha)),
        __float2half_rn(b - __half2float(hb)));
    hi = *reinterpret_cast<uint32_t*>(&th);
    lo = *reinterpret_cast<uint32_t*>(&tl);
}
// ldmatrix x4 address for 128B-row, 8-chunk XOR-swizzled tiles
__device__ __forceinline__ uint32_t ldsm_addr(uint32_t base, int row0, int ch0, int lane) {
    int row = row0 + (lane & 7) + ((lane >> 3) & 1) * 8;
    int ch  = ch0 + (lane >> 4);
    return base + (uint32_t)(row * 128) + (uint32_t)(((ch ^ (row & 7)) & 7) << 4);
}

// ---------------------------------------------------------------------------
// Input convert (3 tensors, fp32 -> fp16) and weight transpose-split (x32)
// ---------------------------------------------------------------------------
struct SP3 { const float* x[3]; __half* h[3]; };
struct TS4 { const float* w[4]; __half* hi[4]; __half* lo[4]; };

__global__ void conv3_kernel(SP3 p, int n4)
{
    int i = blockIdx.x * blockDim.x + threadIdx.x;
    if (i >= n4) return;
    const int z = blockIdx.z;
    float4 v = ((const float4*)p.x[z])[i];
    __half2* hp = (__half2*)(p.h[z] + (size_t)i * 4);
    hp[0] = __floats2half2_rn(v.x, v.y);
    hp[1] = __floats2half2_rn(v.z, v.w);
}

// W [K,N] row-major -> Wt hi/lo [N,K], scaled by 32 (keeps lo fp16-normal)
__global__ void transpose_split4_kernel(TS4 p)
{
    __shared__ float t[32][33];
    const int z = blockIdx.z;
    const float* w = p.w[z];
    int tx = threadIdx.x, ty = threadIdx.y;
    int bx = blockIdx.x * 32, by = blockIdx.y * 32;
#pragma unroll
    for (int i = 0; i < 4; i++)
        t[ty + i * 8][tx] = w[(size_t)(by + ty + i * 8) * D_ + bx + tx];
    __syncthreads();
#pragma unroll
    for (int i = 0; i < 4; i++) {
        float v = t[tx][ty + i * 8] * 32.0f;
        __half h = __float2half_rn(v);
        __half l = __float2half_rn(v - __half2float(h));
        size_t o = (size_t)(bx + ty + i * 8) * D_ + by + tx;
        p.hi[z][o] = h; p.lo[z][o] = l;
    }
}

// ---------------------------------------------------------------------------
// HMMA fp16 GEMM: C = A_fp16 @ (Whi+Wlo)^T / 32 + bias.  2 MMA terms.
// BK=64, 3-stage cp.async pipeline, 128x128 tile, 8 warps (2x4).
// Epilogue emits fp32, fp16 single, or fp16 hi/lo split.
// ---------------------------------------------------------------------------
#define BK_        64
#define G_A        0
#define G_WH       16384
#define G_WL       32768
#define G_STAGE    49152
#define G_NBUF     3
#define GSMEM      (G_NBUF * G_STAGE)     // 147456
#define NSTAGES    (D_ / BK_)             // 16
#define INV32      0.03125f

struct GArgs {
    const __half *A, *Wh, *Wl;
    const float* bias;
    float* Cf;
    __half *Ch, *Cl;
};
struct GBatch { GArgs g[3]; };

__device__ __forceinline__ void g_load_stage(uint32_t sb, const GArgs& a,
                                             int m0, int n0, int kt, int tid)
{
#pragma unroll
    for (int i = 0; i < 4; i++) {
        int c = tid + i * 256;              // 0..1023
        int r = c >> 3, ch = c & 7;
        uint32_t so = (uint32_t)(r * 128 + (((ch ^ (r & 7)) & 7) << 4));
        const size_t ga = (size_t)(m0 + r) * D_ + kt + ch * 8;
        const size_t gb = (size_t)(n0 + r) * D_ + kt + ch * 8;
        cp16(sb + G_A  + so, a.A  + ga);
        cp16(sb + G_WH + so, a.Wh + gb);
        cp16(sb + G_WL + so, a.Wl + gb);
    }
}

__global__ __launch_bounds__(256, 1)
void gemm_hmma(GBatch batch)
{
    extern __shared__ char smem[];
    const uint32_t su = smem_to_u32(smem);
    const GArgs a = batch.g[blockIdx.z];
    const int tid = threadIdx.x, lane = tid & 31;
    const int m0 = blockIdx.y * 128, n0 = blockIdx.x * 128;
    const int warpM = (tid >> 5) & 1;     // 64 rows each
    const int warpN = tid >> 6;           // 32 cols each

    float acc[4][4][4];
#pragma unroll
    for (int i = 0; i < 4; i++)
#pragma unroll
        for (int j = 0; j < 4; j++)
#pragma unroll
            for (int r = 0; r < 4; r++) acc[i][j][r] = 0.0f;

#pragma unroll
    for (int s = 0; s < G_NBUF; s++) {
        g_load_stage(su + s * G_STAGE, a, m0, n0, s * BK_, tid);
        cp_commit();
    }

    uint32_t sb = su;
    int buf = 0;
    for (int c = 0; c < NSTAGES; c++) {
        asm volatile("cp.async.wait_group 2;\n" ::: "memory");
        __syncthreads();

#pragma unroll
        for (int kc = 0; kc < 4; kc++) {
            uint32_t ah[4][4], wh[2][4], wl[2][4];
#pragma unroll
            for (int i = 0; i < 4; i++)
                ldsm_x4(ah[i], ldsm_addr(sb + G_A, warpM * 64 + i * 16, kc * 2, lane));
#pragma unroll
            for (int j = 0; j < 2; j++) {
                ldsm_x4(wh[j], ldsm_addr(sb + G_WH, warpN * 32 + j * 16, kc * 2, lane));
                ldsm_x4(wl[j], ldsm_addr(sb + G_WL, warpN * 32 + j * 16, kc * 2, lane));
            }
#pragma unroll
            for (int i = 0; i < 4; i++)
#pragma unroll
                for (int j = 0; j < 4; j++) {
                    const int g = j >> 1, p = j & 1;
                    mma_f16(acc[i][j], ah[i], wh[g][p], wh[g][p + 2]);
                    mma_f16(acc[i][j], ah[i], wl[g][p], wl[g][p + 2]);
                }
        }
        __syncthreads();
        if (c + G_NBUF < NSTAGES)
            g_load_stage(sb, a, m0, n0, (c + G_NBUF) * BK_, tid);
        cp_commit();   // always commit so wait_group 2 stays uniform

        buf = (buf == G_NBUF - 1) ? 0 : buf + 1;
        sb = su + (uint32_t)buf * G_STAGE;
    }

    const int crow = lane >> 2, ccol = (lane & 3) * 2;
#pragma unroll
    for (int i = 0; i < 4; i++) {
        const int gr = m0 + warpM * 64 + i * 16 + crow;
#pragma unroll
        for (int j = 0; j < 4; j++) {
            const int gc = n0 + warpN * 32 + j * 8 + ccol;
            const float b0 = __ldg(a.bias + gc), b1 = __ldg(a.bias + gc + 1);
            float v0 = acc[i][j][0] * INV32 + b0, v1 = acc[i][j][1] * INV32 + b1;
            float v2 = acc[i][j][2] * INV32 + b0, v3 = acc[i][j][3] * INV32 + b1;
            if (a.Cf) {
                *(float2*)(a.Cf + (size_t)gr * D_ + gc)       = make_float2(v0, v1);
                *(float2*)(a.Cf + (size_t)(gr + 8) * D_ + gc) = make_float2(v2, v3);
            } else if (a.Cl) {       // fp16 hi/lo split (K projection)
                uint32_t h01, l01, h23, l23;
                pk_split2h(v0, v1, h01, l01);
                pk_split2h(v2, v3, h23, l23);
                *(uint32_t*)(a.Ch + (size_t)gr * D_ + gc)       = h01;
                *(uint32_t*)(a.Ch + (size_t)(gr + 8) * D_ + gc) = h23;
                *(uint32_t*)(a.Cl + (size_t)gr * D_ + gc)       = l01;
                *(uint32_t*)(a.Cl + (size_t)(gr + 8) * D_ + gc) = l23;
            } else {                 // fp16 single (Q, V projections)
                *(uint32_t*)(a.Ch + (size_t)gr * D_ + gc)       = pk_h2(v0, v1);
                *(uint32_t*)(a.Ch + (size_t)(gr + 8) * D_ + gc) = pk_h2(v2, v3);
            }
        }
    }
}

// ---------------------------------------------------------------------------
// HMMA flash attention (fp16). CTA: 64 q-rows, 4 warps, 2 CTAs/SM.
// kv tile 64, double buffer. S = Q@(Khi+Klo)^T (2 terms);
// PV = (Phi+Plo)@V (2 terms). O emitted single fp16.
// smem: Q 8KB + 2 stages x 24KB = 56KB.
// ---------------------------------------------------------------------------
#define ATT_STAGE  24576
#define ATT_SMEM   (8192 + 2 * ATT_STAGE)    // 57344
#define NKV        (S_ / 64)                  // 32

__device__ __forceinline__ void att_load_kv(uint32_t stg_base,
    const __half* __restrict__ Kh, const __half* __restrict__ Kl,
    const __half* __restrict__ V,
    size_t rowbase, int jt, int col0, int tid)
{
#pragma unroll
    for (int i = 0; i < 4; i++) {
        int c = tid + i * 128;             // 0..511
        int r = c >> 3, ch = c & 7;
        uint32_t so = (uint32_t)(r * 128 + (((ch ^ (r & 7)) & 7) << 4));
        const size_t g = (rowbase + jt + r) * D_ + col0 + ch * 8;
        cp16(stg_base + 0     + so, Kh + g);
        cp16(stg_base + 8192  + so, Kl + g);
        cp16(stg_base + 16384 + so, V  + g);
    }
}

__global__ __launch_bounds__(128, 2)
void attn_hmma(const __half* __restrict__ Q,
               const __half* __restrict__ Kh, const __half* __restrict__ Kl,
               const __half* __restrict__ V,
               __half* __restrict__ O)
{
    extern __shared__ char smem[];
    const uint32_t su = smem_to_u32(smem);
    const int tid = threadIdx.x, lane = tid & 31, warp = tid >> 5;
    const int q0 = blockIdx.x * 64;
    const int h  = blockIdx.y, b = blockIdx.z;
    const size_t rowbase = (size_t)b * S_;
    const int col0 = h * DK_;

    const uint32_t QS  = su;
    const uint32_t STG = su + 8192;

    // Q tile (fp16 single), swizzled 128B rows
#pragma unroll
    for (int i = 0; i < 4; i++) {
        int c = tid + i * 128;             // 0..511
        int r = c >> 3, ch = c & 7;
        uint32_t so = (uint32_t)(r * 128 + (((ch ^ (r & 7)) & 7) << 4));
        cp16(QS + so, Q + (rowbase + q0 + r) * D_ + col0 + ch * 8);
    }
    cp_commit();
    att_load_kv(STG, Kh, Kl, V, rowbase, 0, col0, tid);
    cp_commit();
    att_load_kv(STG + ATT_STAGE, Kh, Kl, V, rowbase, 64, col0, tid);
    cp_commit();

    asm volatile("cp.async.wait_group 2;\n" ::: "memory");
    __syncthreads();

    uint32_t qf[4][4];
#pragma unroll
    for (int kc = 0; kc < 4; kc++)
        ldsm_x4(qf[kc], ldsm_addr(QS, warp * 16, kc * 2, lane));

    float oacc[8][4];
#pragma unroll
    for (int j = 0; j < 8; j++)
#pragma unroll
        for (int i = 0; i < 4; i++) oacc[j][i] = 0.0f;
    float m0 = -3.0e38f, m1 = -3.0e38f, l0 = 0.0f, l1 = 0.0f;

    for (int c = 0; c < NKV; c++) {
        if (c < NKV - 1)
            asm volatile("cp.async.wait_group 1;\n" ::: "memory");
        else
            asm volatile("cp.async.wait_group 0;\n" ::: "memory");
        __syncthreads();

        const uint32_t KB = STG + (uint32_t)(c & 1) * ATT_STAGE;
        const uint32_t KBL = KB + 8192, VB = KB + 16384;

        // ---- S = Q @ (Khi + Klo)^T, S tile [16 q, 64 kv] per warp
        float sacc[8][4];
#pragma unroll
        for (int j = 0; j < 8; j++)
#pragma unroll
            for (int i = 0; i < 4; i++) sacc[j][i] = 0.0f;

#pragma unroll
        for (int kc = 0; kc < 4; kc++) {
            uint32_t kh[4][4], kl[4][4];
#pragma unroll
            for (int ng = 0; ng < 4; ng++) {
                ldsm_x4(kh[ng], ldsm_addr(KB,  ng * 16, kc * 2, lane));
                ldsm_x4(kl[ng], ldsm_addr(KBL, ng * 16, kc * 2, lane));
            }
#pragma unroll
            for (int j = 0; j < 8; j++) {
                const int g = j >> 1, p = j & 1;
                mma_f16(sacc[j], qf[kc], kh[g][p], kh[g][p + 2]);
                mma_f16(sacc[j], qf[kc], kl[g][p], kl[g][p + 2]);
            }
        }

        // ---- online softmax in registers (rows lane>>2 and +8)
#pragma unroll
        for (int j = 0; j < 8; j++)
#pragma unroll
            for (int i = 0; i < 4; i++) sacc[j][i] *= 0.125f;

        float mx0 = -3.0e38f, mx1 = -3.0e38f;
#pragma unroll
        for (int j = 0; j < 8; j++) {
            mx0 = fmaxf(mx0, fmaxf(sacc[j][0], sacc[j][1]));
            mx1 = fmaxf(mx1, fmaxf(sacc[j][2], sacc[j][3]));
        }
        mx0 = fmaxf(mx0, __shfl_xor_sync(0xffffffffu, mx0, 1));
        mx0 = fmaxf(mx0, __shfl_xor_sync(0xffffffffu, mx0, 2));
        mx1 = fmaxf(mx1, __shfl_xor_sync(0xffffffffu, mx1, 1));
        mx1 = fmaxf(mx1, __shfl_xor_sync(0xffffffffu, mx1, 2));

        float mn0 = fmaxf(m0, mx0), mn1 = fmaxf(m1, mx1);
        float corr0 = __expf(m0 - mn0), corr1 = __expf(m1 - mn1);
        m0 = mn0; m1 = mn1;

        float s0 = 0.0f, s1 = 0.0f;
#pragma unroll
        for (int j = 0; j < 8; j++) {
            sacc[j][0] = __expf(sacc[j][0] - mn0);
            sacc[j][1] = __expf(sacc[j][1] - mn0);
            sacc[j][2] = __expf(sacc[j][2] - mn1);
            sacc[j][3] = __expf(sacc[j][3] - mn1);
            s0 += sacc[j][0] + sacc[j][1];
            s1 += sacc[j][2] + sacc[j][3];
        }
        s0 += __shfl_xor_sync(0xffffffffu, s0, 1);
        s0 += __shfl_xor_sync(0xffffffffu, s0, 2);
        s1 += __shfl_xor_sync(0xffffffffu, s1, 1);
        s1 += __shfl_xor_sync(0xffffffffu, s1, 2);
        l0 = l0 * corr0 + s0;
        l1 = l1 * corr1 + s1;

#pragma unroll
        for (int j = 0; j < 8; j++) {
            oacc[j][0] *= corr0; oacc[j][1] *= corr0;
            oacc[j][2] *= corr1; oacc[j][3] *= corr1;
        }

        // ---- O += (Phi + Plo) @ V
#pragma unroll
        for (int kc = 0; kc < 4; kc++) {
            uint32_t ph[4], pl[4];
            pk_split2h(sacc[2 * kc][0],     sacc[2 * kc][1],     ph[0], pl[0]);
            pk_split2h(sacc[2 * kc][2],     sacc[2 * kc][3],     ph[1], pl[1]);
            pk_split2h(sacc[2 * kc + 1][0], sacc[2 * kc + 1][1], ph[2], pl[2]);
            pk_split2h(sacc[2 * kc + 1][2], sacc[2 * kc + 1][3], ph[3], pl[3]);
#pragma unroll
            for (int dg = 0; dg < 4; dg++) {
                uint32_t vf[4];
                ldsm_x4_t(vf, ldsm_addr(VB, kc * 16, dg * 2, lane));
                mma_f16(oacc[2 * dg],     ph, vf[0], vf[1]);
                mma_f16(oacc[2 * dg + 1], ph, vf[2], vf[3]);
                mma_f16(oacc[2 * dg],     pl, vf[0], vf[1]);
                mma_f16(oacc[2 * dg + 1], pl, vf[2], vf[3]);
            }
        }

        __syncthreads();
        if (c + 2 < NKV) {
            att_load_kv(STG + (uint32_t)(c & 1) * ATT_STAGE,
                        Kh, Kl, V, rowbase, (c + 2) * 64, col0, tid);
            cp_commit();
        }
    }

    // ---- epilogue: normalize, store fp16 single
    const float inv0 = 1.0f / l0, inv1 = 1.0f / l1;
    const int r0 = warp * 16 + (lane >> 2);
    const int c0 = (lane & 3) * 2;
#pragma unroll
    for (int j = 0; j < 8; j++) {
        const int dcol = col0 + j * 8 + c0;
        *(uint32_t*)(O + (rowbase + q0 + r0) * D_ + dcol) =
            pk_h2(oacc[j][0] * inv0, oacc[j][1] * inv0);
        *(uint32_t*)(O + (rowbase + q0 + r0 + 8) * D_ + dcol) =
            pk_h2(oacc[j][2] * inv1, oacc[j][3] * inv1);
    }
}

// ---------------------------------------------------------------------------
// kernel_launch: 5 launches total
// ---------------------------------------------------------------------------
extern "C" void kernel_launch(void* const* d_in, const int* in_sizes, int n_in,
                              void* d_out, int out_size)
{
    const float* q  = (const float*)d_in[0];
    const float* k  = (const float*)d_in[1];
    const float* v  = (const float*)d_in[2];
    const float* wq = (const float*)d_in[3];
    const float* bq = (const float*)d_in[4];
    const float* wk = (const float*)d_in[5];
    const float* bk = (const float*)d_in[6];
    const float* wv = (const float*)d_in[7];
    const float* bv = (const float*)d_in[8];
    const float* wo = (const float*)d_in[9];
    const float* bo = (const float*)d_in[10];
    float* out = (float*)d_out;

    __half *Xq, *Xk, *Xv;
    __half *WQh, *WQl, *WKh, *WKl, *WVh, *WVl, *WOh, *WOl;
    __half *Qp, *Khp, *Klp, *Vp;
    cudaGetSymbolAddress((void**)&Xq,  g_Xq);
    cudaGetSymbolAddress((void**)&Xk,  g_Xk);
    cudaGetSymbolAddress((void**)&Xv,  g_Xv);
    cudaGetSymbolAddress((void**)&WQh, g_WQh);
    cudaGetSymbolAddress((void**)&WQl, g_WQl);
    cudaGetSymbolAddress((void**)&WKh, g_WKh);
    cudaGetSymbolAddress((void**)&WKl, g_WKl);
    cudaGetSymbolAddress((void**)&WVh, g_WVh);
    cudaGetSymbolAddress((void**)&WVl, g_WVl);
    cudaGetSymbolAddress((void**)&WOh, g_WOh);
    cudaGetSymbolAddress((void**)&WOl, g_WOl);
    cudaGetSymbolAddress((void**)&Qp,  g_Q);
    cudaGetSymbolAddress((void**)&Khp, g_Kh);
    cudaGetSymbolAddress((void**)&Klp, g_Kl);
    cudaGetSymbolAddress((void**)&Vp,  g_V);

    cudaFuncSetAttribute(gemm_hmma,
                         cudaFuncAttributeMaxDynamicSharedMemorySize, GSMEM);
    cudaFuncSetAttribute(attn_hmma,
                         cudaFuncAttributeMaxDynamicSharedMemorySize, ATT_SMEM);

    // 1) all weight transposes (scaled x32, fp16 hi/lo)
    TS4 ts = {{wq, wk, wv, wo}, {WQh, WKh, WVh, WOh}, {WQl, WKl, WVl, WOl}};
    transpose_split4_kernel<<<dim3(D_ / 32, D_ / 32, 4), dim3(32, 8)>>>(ts);

    // 2) all input converts (fp32 -> fp16)
    const int n4 = M_ * D_ / 4;
    SP3 sp = {{q, k, v}, {Xq, Xk, Xv}};
    conv3_kernel<<<dim3(n4 / 256, 1, 3), 256>>>(sp, n4);

    // 3) batched Q/K/V projections
    GBatch pb;
    pb.g[0] = {Xq, WQh, WQl, bq, nullptr, Qp,  nullptr};  // Q: fp16 single
    pb.g[1] = {Xk, WKh, WKl, bk, nullptr, Khp, Klp};      // K: fp16 hi/lo
    pb.g[2] = {Xv, WVh, WVl, bv, nullptr, Vp,  nullptr};  // V: fp16 single
    gemm_hmma<<<dim3(D_ / 128, M_ / 128, 3), 256, GSMEM>>>(pb);

    // 4) attention -> O (fp16 single) into Xq (done with its input role)
    attn_hmma<<<dim3(S_ / 64, H_, B_), 128, ATT_SMEM>>>(
        Qp, Khp, Klp, Vp, Xq);

    // 5) output projection -> fp32 out
    GBatch ob;
    ob.g[0] = {Xq, WOh, WOl, bo, out, nullptr, nullptr};
    ob.g[1] = ob.g[0];
    ob.g[2] = ob.g[0];
    gemm_hmma<<<dim3(D_ / 128, M_ / 128, 1), 256, GSMEM>>>(ob);
}